// round 1
// baseline (speedup 1.0000x reference)
#include <cuda_runtime.h>
#include <math.h>

// ---------------------------------------------------------------------------
// SimpleMetaNet: out = rescale * dyn_scale * softmax(f(g)) * g
// where f is a scalar->scalar ReLU MLP (1->32->32->1), hence exactly
// piecewise-linear. We build the exact PWL table on device, then the heavy
// passes are pure streaming: logit = a_s*x + c_s  (LUT lookup + FMA).
//
// Softmax normalizer cancels:
//   out_i = rescale * grad_norm/(masked_norm+eps) * e_i*g_i / S
//   e_i = exp(l_i - m), S = sum e_i, masked_norm = sqrt(sum (e_i g_i)^2)/S
// ---------------------------------------------------------------------------

#define H 32
#define NCAND 2048        // max breakpoints (true bound: 32 + 32*33 = 1088)
#define LUTN 4096
#define GRID1 2048
#define TPB 256
#define CLAMPV 1024.0f    // eval-point clamp: keeps |a*p| small -> precise c

// ---- device scratch (no allocation allowed) ----
__device__ int            g_n1;
__device__ float          g_l1k[H];
__device__ int            g_ncand;
__device__ float          g_cand[NCAND];
__device__ float          g_bp[NCAND];
__device__ int            g_nbp;
__device__ float2         g_ac[NCAND + 1];        // (slope a, intercept c) per segment
__device__ unsigned short g_lut[LUTN];
__device__ float          g_psum[GRID1], g_pmin[GRID1], g_pmax[GRID1];
__device__ float          g_pS[GRID1],   g_ps2[GRID1];
__device__ float          g_sumg2, g_m, g_lutlo, g_lutinv, g_kc;

// ===========================================================================
// K0a: layer-1 kinks t_j = -b1[j]/W1[j], sorted; seed candidate list.
// ===========================================================================
__global__ void k0a(const float* __restrict__ W1, const float* __restrict__ b1) {
    __shared__ float loc[H];
    __shared__ int cnt;
    int tid = threadIdx.x;
    if (tid == 0) { cnt = 0; g_ncand = 0; }
    __syncthreads();
    if (tid < H) {
        float w = W1[tid];
        if (w != 0.0f) {
            int p = atomicAdd(&cnt, 1);
            loc[p] = -b1[tid] / w;
        }
    }
    __syncthreads();
    if (tid == 0) {
        int n = cnt;
        for (int i = 1; i < n; i++) {           // insertion sort (n<=32)
            float v = loc[i]; int j = i - 1;
            while (j >= 0 && loc[j] > v) { loc[j + 1] = loc[j]; j--; }
            loc[j + 1] = v;
        }
        for (int i = 0; i < n; i++) { g_l1k[i] = loc[i]; g_cand[i] = loc[i]; }
        g_n1 = n; g_ncand = n;
    }
}

// ===========================================================================
// K0b: for each (hidden unit k, layer-1 interval), z_k(x) is linear; find its
// root via dual-number eval at an interior point. Append as breakpoint
// candidate if strictly inside the interval. (Spurious extras are harmless:
// each segment's coefficients are computed independently in K0d.)
// ===========================================================================
__global__ void k0b(const float* __restrict__ W1, const float* __restrict__ b1,
                    const float* __restrict__ W2, const float* __restrict__ b2) {
    int n1 = g_n1;
    int total = H * (n1 + 1);
    int p = blockIdx.x * blockDim.x + threadIdx.x;
    if (p >= total) return;
    int k  = p / (n1 + 1);
    int iv = p - k * (n1 + 1);
    float u = (iv == 0)  ? -1e30f : g_l1k[iv - 1];
    float v = (iv == n1) ?  1e30f : g_l1k[iv];
    if (!(u < v)) return;                        // zero-width (duplicate kinks)
    float lo = fmaxf(u, -CLAMPV), hi = fminf(v, CLAMPV);
    float q  = (lo < hi) ? 0.5f * (lo + hi) : (0.5f * u + 0.5f * v);

    float z = b2[k], dz = 0.0f;
    #pragma unroll
    for (int j = 0; j < H; j++) {
        float pre = fmaf(W1[j], q, b1[j]);
        float w2  = W2[j * H + k];
        if (pre > 0.0f) { z = fmaf(pre, w2, z); dz = fmaf(W1[j], w2, dz); }
    }
    if (dz != 0.0f) {
        float r = q - z / dz;                    // exact root of linear z on (u,v)
        if (r > u && r < v) {
            int idx = atomicAdd(&g_ncand, 1);
            g_cand[idx] = r;
        }
    }
}

// ===========================================================================
// K0c: bitonic sort of candidates (padded with +huge). Sorting makes the
// atomic-append order irrelevant -> deterministic table.
// ===========================================================================
__global__ void k0c() {
    __shared__ float s[NCAND];
    int tid = threadIdx.x;
    int n = g_ncand;
    for (int i = tid; i < NCAND; i += blockDim.x)
        s[i] = (i < n) ? g_cand[i] : 3.0e38f;
    __syncthreads();
    for (int k = 2; k <= NCAND; k <<= 1) {
        for (int j = k >> 1; j > 0; j >>= 1) {
            for (int i = tid; i < NCAND; i += blockDim.x) {
                int ixj = i ^ j;
                if (ixj > i) {
                    float a = s[i], b = s[ixj];
                    bool up = ((i & k) == 0);
                    if ((a > b) == up) { s[i] = b; s[ixj] = a; }
                }
            }
            __syncthreads();
        }
    }
    for (int i = tid; i < NCAND; i += blockDim.x) g_bp[i] = s[i];
    if (tid == 0) g_nbp = n;
}

// ===========================================================================
// K0d: per segment, forward-mode dual eval of the full MLP at an interior
// point p -> exact (f, f') for the active ReLU pattern -> a = f', c = f - f'*p.
// ===========================================================================
__global__ void k0d(const float* __restrict__ W1, const float* __restrict__ b1,
                    const float* __restrict__ W2, const float* __restrict__ b2,
                    const float* __restrict__ W3, const float* __restrict__ b3) {
    int nbp  = g_nbp;
    int nseg = nbp + 1;
    for (int s = blockIdx.x * blockDim.x + threadIdx.x; s < nseg;
         s += gridDim.x * blockDim.x) {
        float u = (s == 0)   ? -1e30f : g_bp[s - 1];
        float v = (s == nbp) ?  1e30f : g_bp[s];
        float lo = fmaxf(u, -CLAMPV), hi = fminf(v, CLAMPV);
        float p  = (lo <= hi) ? 0.5f * (lo + hi) : (0.5f * u + 0.5f * v);

        float h[H], dh[H];
        #pragma unroll
        for (int j = 0; j < H; j++) {
            float pre = fmaf(W1[j], p, b1[j]);
            bool on = pre > 0.0f;
            h[j]  = on ? pre   : 0.0f;
            dh[j] = on ? W1[j] : 0.0f;
        }
        float f = b3[0], df = 0.0f;
        for (int k = 0; k < H; k++) {
            float z = b2[k], dz = 0.0f;
            #pragma unroll
            for (int j = 0; j < H; j++) {
                float w2 = W2[j * H + k];
                z  = fmaf(h[j],  w2, z);
                dz = fmaf(dh[j], w2, dz);
            }
            if (z > 0.0f) {
                float w3 = W3[k];
                f  = fmaf(z,  w3, f);
                df = fmaf(dz, w3, df);
            }
        }
        g_ac[s] = make_float2(df, fmaf(-df, p, f));
    }
}

// ---- block reductions (256 threads) ----
__device__ __forceinline__ float bsum256(float v, float* sh) {
    for (int o = 16; o; o >>= 1) v += __shfl_down_sync(0xffffffffu, v, o);
    int w = threadIdx.x >> 5;
    if ((threadIdx.x & 31) == 0) sh[w] = v;
    __syncthreads();
    if (threadIdx.x < 8) {
        v = sh[threadIdx.x];
        for (int o = 4; o; o >>= 1) v += __shfl_down_sync(0xffu, v, o);
    }
    return v;
}
__device__ __forceinline__ float bmin256(float v, float* sh) {
    for (int o = 16; o; o >>= 1) v = fminf(v, __shfl_down_sync(0xffffffffu, v, o));
    int w = threadIdx.x >> 5;
    if ((threadIdx.x & 31) == 0) sh[w] = v;
    __syncthreads();
    if (threadIdx.x < 8) {
        v = sh[threadIdx.x];
        for (int o = 4; o; o >>= 1) v = fminf(v, __shfl_down_sync(0xffu, v, o));
    }
    return v;
}
__device__ __forceinline__ float bmax256(float v, float* sh) {
    for (int o = 16; o; o >>= 1) v = fmaxf(v, __shfl_down_sync(0xffffffffu, v, o));
    int w = threadIdx.x >> 5;
    if ((threadIdx.x & 31) == 0) sh[w] = v;
    __syncthreads();
    if (threadIdx.x < 8) {
        v = sh[threadIdx.x];
        for (int o = 4; o; o >>= 1) v = fmaxf(v, __shfl_down_sync(0xffu, v, o));
    }
    return v;
}

// ===========================================================================
// K1: streaming pass 1 — partial sum(g^2), min(g), max(g)
// ===========================================================================
__global__ void __launch_bounds__(TPB) k1(const float* __restrict__ g, int N) {
    __shared__ float shA[8], shB[8], shC[8];
    float sum = 0.0f, mn = 3.4e38f, mx = -3.4e38f;
    int gt = blockIdx.x * blockDim.x + threadIdx.x;
    int stride = gridDim.x * blockDim.x;
    int N4 = N >> 2;
    const float4* g4 = (const float4*)g;
    for (int i = gt; i < N4; i += stride) {
        float4 v = g4[i];
        sum = fmaf(v.x, v.x, sum); sum = fmaf(v.y, v.y, sum);
        sum = fmaf(v.z, v.z, sum); sum = fmaf(v.w, v.w, sum);
        mn = fminf(mn, fminf(fminf(v.x, v.y), fminf(v.z, v.w)));
        mx = fmaxf(mx, fmaxf(fmaxf(v.x, v.y), fmaxf(v.z, v.w)));
    }
    for (int i = (N4 << 2) + gt; i < N; i += stride) {
        float x = g[i];
        sum = fmaf(x, x, sum); mn = fminf(mn, x); mx = fmaxf(mx, x);
    }
    float bs = bsum256(sum, shA);
    float bm = bmin256(mn,  shB);
    float bx = bmax256(mx,  shC);
    if (threadIdx.x == 0) {
        g_psum[blockIdx.x] = bs; g_pmin[blockIdx.x] = bm; g_pmax[blockIdx.x] = bx;
    }
}

// ---- global-memory logit eval (used only in tiny K2) ----
__device__ __forceinline__ int countLE_g(float x, int nbp) {
    int lo = 0, hi = nbp;
    while (lo < hi) { int mid = (lo + hi) >> 1; if (g_bp[mid] <= x) lo = mid + 1; else hi = mid; }
    return lo;
}
__device__ __forceinline__ float evalg(float x, int nbp) {
    float2 ac = g_ac[countLE_g(x, nbp)];
    return fmaf(ac.x, x, ac.y);
}

// ===========================================================================
// K2: finalize pass-1 reductions; m = max logit over [gmin,gmax] (PWL max is
// attained at endpoints/kinks — no data pass needed); build segment LUT.
// ===========================================================================
__global__ void k2() {
    __shared__ float s1[1024], s2s[1024], s3[1024];
    int tid = threadIdx.x;
    s1[tid]  = g_psum[tid] + g_psum[tid + 1024];
    s2s[tid] = fminf(g_pmin[tid], g_pmin[tid + 1024]);
    s3[tid]  = fmaxf(g_pmax[tid], g_pmax[tid + 1024]);
    __syncthreads();
    for (int o = 512; o; o >>= 1) {
        if (tid < o) {
            s1[tid]  += s1[tid + o];
            s2s[tid]  = fminf(s2s[tid], s2s[tid + o]);
            s3[tid]   = fmaxf(s3[tid],  s3[tid + o]);
        }
        __syncthreads();
    }
    float gmin = s2s[0], gmax = s3[0];
    if (tid == 0) g_sumg2 = s1[0];
    __syncthreads();

    int nbp = g_nbp;
    float lm = -3.4e38f;
    for (int i = tid; i < nbp; i += blockDim.x) {
        float t = g_bp[i];
        if (t > gmin && t < gmax) lm = fmaxf(lm, evalg(t, nbp));
    }
    if (tid == 0) lm = fmaxf(lm, fmaxf(evalg(gmin, nbp), evalg(gmax, nbp)));
    s1[tid] = lm;
    __syncthreads();
    for (int o = 512; o; o >>= 1) {
        if (tid < o) s1[tid] = fmaxf(s1[tid], s1[tid + o]);
        __syncthreads();
    }

    float w   = gmax - gmin;
    float inv = (w > 0.0f) ? ((float)LUTN) / w : 0.0f;
    for (int c = tid; c < LUTN; c += blockDim.x) {
        float cs = gmin + ((float)c) * (w * (1.0f / (float)LUTN));
        g_lut[c] = (unsigned short)countLE_g(cs, nbp);
    }
    if (tid == 0) { g_m = s1[0]; g_lutlo = gmin; g_lutinv = inv; }
}

// ---- shared-memory logit eval for the streaming passes ----
__device__ __forceinline__ float eval_l(float x, const float* sbp, const float2* sac,
                                        const unsigned short* slut, int nbp,
                                        float lutlo, float lutinv) {
    int c = (int)((x - lutlo) * lutinv);
    c = c < 0 ? 0 : (c > LUTN - 1 ? LUTN - 1 : c);
    int s = slut[c];
    while (s < nbp && sbp[s] <= x) s++;   // almost always 0 iterations
    float2 ac = sac[s];
    return fmaf(ac.x, x, ac.y);
}

// ===========================================================================
// K3: streaming pass 2 — partial S = sum exp(l-m), s2 = sum (exp(l-m)*g)^2
// ===========================================================================
__global__ void __launch_bounds__(TPB) k3(const float* __restrict__ g, int N) {
    __shared__ float          sbp[NCAND];
    __shared__ float2         sac[NCAND + 1];
    __shared__ unsigned short slut[LUTN];
    __shared__ float shA[8], shB[8];
    int nbp = g_nbp;
    for (int i = threadIdx.x; i < nbp;     i += blockDim.x) sbp[i] = g_bp[i];
    for (int i = threadIdx.x; i < nbp + 1; i += blockDim.x) sac[i] = g_ac[i];
    for (int i = threadIdx.x; i < LUTN;    i += blockDim.x) slut[i] = g_lut[i];
    float m = g_m, lutlo = g_lutlo, lutinv = g_lutinv;
    __syncthreads();

    float S = 0.0f, q = 0.0f;
    int gt = blockIdx.x * blockDim.x + threadIdx.x;
    int stride = gridDim.x * blockDim.x;
    int N4 = N >> 2;
    const float4* g4 = (const float4*)g;
    for (int i = gt; i < N4; i += stride) {
        float4 v = g4[i];
        #pragma unroll
        for (int u = 0; u < 4; u++) {
            float x = (u == 0) ? v.x : (u == 1) ? v.y : (u == 2) ? v.z : v.w;
            float l = eval_l(x, sbp, sac, slut, nbp, lutlo, lutinv);
            float e = __expf(l - m);
            S += e;
            float t = e * x;
            q = fmaf(t, t, q);
        }
    }
    for (int i = (N4 << 2) + gt; i < N; i += stride) {
        float x = g[i];
        float l = eval_l(x, sbp, sac, slut, nbp, lutlo, lutinv);
        float e = __expf(l - m);
        S += e; float t = e * x; q = fmaf(t, t, q);
    }
    float bS = bsum256(S, shA);
    float bq = bsum256(q, shB);
    if (threadIdx.x == 0) { g_pS[blockIdx.x] = bS; g_ps2[blockIdx.x] = bq; }
}

// ===========================================================================
// K4: finalize -> single output scale  kc = rescale*dyn/S
// ===========================================================================
__global__ void k4(const float* __restrict__ rescale) {
    __shared__ float a[1024], b[1024];
    int tid = threadIdx.x;
    a[tid] = g_pS[tid]  + g_pS[tid + 1024];
    b[tid] = g_ps2[tid] + g_ps2[tid + 1024];
    __syncthreads();
    for (int o = 512; o; o >>= 1) {
        if (tid < o) { a[tid] += a[tid + o]; b[tid] += b[tid + o]; }
        __syncthreads();
    }
    if (tid == 0) {
        float S = a[0], s2 = b[0];
        float gn = sqrtf(g_sumg2);
        float mnorm = sqrtf(s2) / S;
        float dyn = (mnorm > 1e-8f) ? gn / (mnorm + 1e-8f) : 1.0f;
        g_kc = rescale[0] * dyn / S;
    }
}

// ===========================================================================
// K5: streaming pass 3 — out_i = kc * exp(l_i - m) * g_i
// ===========================================================================
__global__ void __launch_bounds__(TPB) k5(const float* __restrict__ g,
                                          float* __restrict__ out, int N) {
    __shared__ float          sbp[NCAND];
    __shared__ float2         sac[NCAND + 1];
    __shared__ unsigned short slut[LUTN];
    int nbp = g_nbp;
    for (int i = threadIdx.x; i < nbp;     i += blockDim.x) sbp[i] = g_bp[i];
    for (int i = threadIdx.x; i < nbp + 1; i += blockDim.x) sac[i] = g_ac[i];
    for (int i = threadIdx.x; i < LUTN;    i += blockDim.x) slut[i] = g_lut[i];
    float m = g_m, lutlo = g_lutlo, lutinv = g_lutinv, kc = g_kc;
    __syncthreads();

    int gt = blockIdx.x * blockDim.x + threadIdx.x;
    int stride = gridDim.x * blockDim.x;
    int N4 = N >> 2;
    const float4* g4 = (const float4*)g;
    float4* o4 = (float4*)out;
    for (int i = gt; i < N4; i += stride) {
        float4 v = g4[i];
        float4 r;
        r.x = kc * __expf(eval_l(v.x, sbp, sac, slut, nbp, lutlo, lutinv) - m) * v.x;
        r.y = kc * __expf(eval_l(v.y, sbp, sac, slut, nbp, lutlo, lutinv) - m) * v.y;
        r.z = kc * __expf(eval_l(v.z, sbp, sac, slut, nbp, lutlo, lutinv) - m) * v.z;
        r.w = kc * __expf(eval_l(v.w, sbp, sac, slut, nbp, lutlo, lutinv) - m) * v.w;
        o4[i] = r;
    }
    for (int i = (N4 << 2) + gt; i < N; i += stride) {
        float x = g[i];
        out[i] = kc * __expf(eval_l(x, sbp, sac, slut, nbp, lutlo, lutinv) - m) * x;
    }
}

// ===========================================================================
extern "C" void kernel_launch(void* const* d_in, const int* in_sizes, int n_in,
                              void* d_out, int out_size) {
    const float* grad    = (const float*)d_in[0];
    const float* W1      = (const float*)d_in[1];
    const float* b1      = (const float*)d_in[2];
    const float* W2      = (const float*)d_in[3];
    const float* b2      = (const float*)d_in[4];
    const float* W3      = (const float*)d_in[5];
    const float* b3      = (const float*)d_in[6];
    const float* rescale = (const float*)d_in[7];
    int N = in_sizes[0];

    k0a<<<1, 32>>>(W1, b1);
    k0b<<<9, 128>>>(W1, b1, W2, b2);
    k0c<<<1, 1024>>>();
    k0d<<<9, 128>>>(W1, b1, W2, b2, W3, b3);
    k1<<<GRID1, TPB>>>(grad, N);
    k2<<<1, 1024>>>();
    k3<<<GRID1, TPB>>>(grad, N);
    k4<<<1, 1024>>>(rescale);
    k5<<<GRID1, TPB>>>(grad, (float*)d_out, N);
}

// round 2
// speedup vs baseline: 1.7993x; 1.7993x over previous
#include <cuda_runtime.h>
#include <math.h>

// ---------------------------------------------------------------------------
// SimpleMetaNet: out = rescale * dyn_scale * softmax(f(g)) * g,
// f = scalar ReLU MLP (1->32->32->1) == exact piecewise-linear function.
// Build exact PWL segment table on device, then:
//   pass A (read g once): online softmax (m, S=sum e, q=sum (e*g)^2) + sum g^2
//   pass C (read g, write out): out = kc * exp(l - m) * g,  kc = rescale*dyn/S
// ---------------------------------------------------------------------------

#define H       32
#define NCAND   1088          // exact bound: 32 + 32*33 = 1088
#define LUTN    2048
#define GRID_MAIN 1184        // 148 SMs * 8 blocks
#define TPB     256
#define CLAMPV  1024.0f

#define NEG_INF __int_as_float(0xff800000u)
#define NANF    __int_as_float(0x7fc00000u)

// ---- device scratch ----
__device__ int    g_n1;
__device__ float  g_l1k[H];
__device__ int    g_ncand;
__device__ float  g_cand[NCAND];
__device__ float  g_bp[NCAND];
__device__ int    g_nbp;
__device__ float2 g_ac[NCAND + 1];
__device__ float2 g_lutf2[LUTN];
__device__ float  g_lutlo, g_lutinv;
__device__ float  g_pm[GRID_MAIN], g_pS[GRID_MAIN], g_pq[GRID_MAIN], g_pg2[GRID_MAIN];
__device__ float  g_m, g_kc;

// ===========================================================================
// k0a: layer-1 kinks t_j = -b1[j]/W1[j], sorted (tiny); seed candidates.
// ===========================================================================
__global__ void k0a(const float* __restrict__ W1, const float* __restrict__ b1) {
    __shared__ float loc[H];
    __shared__ int cnt;
    int tid = threadIdx.x;
    if (tid == 0) { cnt = 0; }
    __syncthreads();
    if (tid < H) {
        float w = W1[tid];
        if (w != 0.0f) { int p = atomicAdd(&cnt, 1); loc[p] = -b1[tid] / w; }
    }
    __syncthreads();
    if (tid == 0) {
        int n = cnt;
        for (int i = 1; i < n; i++) {
            float v = loc[i]; int j = i - 1;
            while (j >= 0 && loc[j] > v) { loc[j + 1] = loc[j]; j--; }
            loc[j + 1] = v;
        }
        for (int i = 0; i < n; i++) { g_l1k[i] = loc[i]; g_cand[i] = loc[i]; }
        g_n1 = n; g_ncand = n;
    }
}

// ===========================================================================
// k0b: layer-2 kink candidates: root of each linear z_k on each L1 interval.
// ===========================================================================
__global__ void k0b(const float* __restrict__ W1, const float* __restrict__ b1,
                    const float* __restrict__ W2, const float* __restrict__ b2) {
    int n1 = g_n1;
    int total = H * (n1 + 1);
    int p = blockIdx.x * blockDim.x + threadIdx.x;
    if (p >= total) return;
    int k  = p / (n1 + 1);
    int iv = p - k * (n1 + 1);
    float u = (iv == 0)  ? -1e30f : g_l1k[iv - 1];
    float v = (iv == n1) ?  1e30f : g_l1k[iv];
    if (!(u < v)) return;
    float lo = fmaxf(u, -CLAMPV), hi = fminf(v, CLAMPV);
    float q  = (lo < hi) ? 0.5f * (lo + hi) : (0.5f * u + 0.5f * v);

    float z = b2[k], dz = 0.0f;
    #pragma unroll
    for (int j = 0; j < H; j++) {
        float pre = fmaf(W1[j], q, b1[j]);
        float w2  = W2[j * H + k];
        if (pre > 0.0f) { z = fmaf(pre, w2, z); dz = fmaf(W1[j], w2, dz); }
    }
    if (dz != 0.0f) {
        float r = q - z / dz;
        if (r > u && r < v) { int idx = atomicAdd(&g_ncand, 1); g_cand[idx] = r; }
    }
}

// ===========================================================================
// k0sort: rank-count sort, warp per candidate (deterministic result: sorted
// multiset of values is append-order independent).
// ===========================================================================
__global__ void k0sort() {
    int n = g_ncand;
    int w = (blockIdx.x * blockDim.x + threadIdx.x) >> 5;
    int lane = threadIdx.x & 31;
    if (blockIdx.x == 0 && threadIdx.x == 0) g_nbp = n;
    if (w >= n) return;
    float x = g_cand[w];
    int r = 0;
    for (int j = lane; j < n; j += 32) {
        float y = g_cand[j];
        r += (y < x || (y == x && j < w)) ? 1 : 0;
    }
    #pragma unroll
    for (int o = 16; o; o >>= 1) r += __shfl_down_sync(0xffffffffu, r, o);
    if (lane == 0) g_bp[r] = x;
}

// ===========================================================================
// k0d: warp per segment — dual-number MLP eval at segment midpoint.
// Lane j computes layer-1 unit j; lane k computes layer-2 unit k via shfl
// broadcast; warp tree-reduce (f, df). a = f', c = f - f'*p.
// ===========================================================================
__global__ void k0d(const float* __restrict__ W1, const float* __restrict__ b1,
                    const float* __restrict__ W2, const float* __restrict__ b2,
                    const float* __restrict__ W3, const float* __restrict__ b3) {
    int n = g_nbp;
    int nseg = n + 1;
    int s = (blockIdx.x * blockDim.x + threadIdx.x) >> 5;
    int lane = threadIdx.x & 31;
    if (s >= nseg) return;
    float u = (s == 0) ? -1e30f : g_bp[s - 1];
    float v = (s == n) ?  1e30f : g_bp[s];
    float lo = fmaxf(u, -CLAMPV), hi = fminf(v, CLAMPV);
    float p  = (lo <= hi) ? 0.5f * (lo + hi) : (0.5f * u + 0.5f * v);

    float w1 = W1[lane];
    float pre = fmaf(w1, p, b1[lane]);
    bool on = pre > 0.0f;
    float hj = on ? pre : 0.0f;
    float dj = on ? w1  : 0.0f;

    float z = b2[lane], dz = 0.0f;
    #pragma unroll
    for (int j = 0; j < H; j++) {
        float hh = __shfl_sync(0xffffffffu, hj, j);
        float dd = __shfl_sync(0xffffffffu, dj, j);
        float w2 = W2[j * H + lane];
        z  = fmaf(hh, w2, z);
        dz = fmaf(dd, w2, dz);
    }
    float w3 = W3[lane];
    bool zon = z > 0.0f;
    float f  = zon ? z  * w3 : 0.0f;
    float df = zon ? dz * w3 : 0.0f;
    #pragma unroll
    for (int o = 16; o; o >>= 1) {
        f  += __shfl_down_sync(0xffffffffu, f,  o);
        df += __shfl_down_sync(0xffffffffu, df, o);
    }
    if (lane == 0) {
        f += b3[0];
        g_ac[s] = make_float2(df, fmaf(-df, p, f));
    }
}

// ===========================================================================
// k0lut: per-cell (a,c) LUT over domain [bpmin-1, bpmax+1].
// Clean check widened by one cell each side (covers float index wobble).
// Dirty cells encode a binary-search window (s0,s1) packed in the y field.
// ===========================================================================
__global__ void k0lut() {
    __shared__ float sbp[NCAND];
    int n = g_nbp;
    for (int i = threadIdx.x; i < n; i += blockDim.x) sbp[i] = g_bp[i];
    __syncthreads();
    float bmin = (n > 0) ? sbp[0]     : 0.0f;
    float bmax = (n > 0) ? sbp[n - 1] : 0.0f;
    float lo = bmin - 1.0f, hi = bmax + 1.0f;
    float cw = (hi - lo) * (1.0f / (float)LUTN);

    int c = blockIdx.x * blockDim.x + threadIdx.x;
    if (c < LUTN) {
        float wl = fmaf((float)(c - 1), cw, lo);
        float wr = fmaf((float)(c + 2), cw, lo);
        int s0, s1;
        { int a = 0, b = n; while (a < b) { int m = (a + b) >> 1; if (sbp[m] <= wl) a = m + 1; else b = m; } s0 = a; }
        { int a = 0, b = n; while (a < b) { int m = (a + b) >> 1; if (sbp[m] <= wr) a = m + 1; else b = m; } s1 = a; }
        float2 e;
        if (s0 == s1) e = g_ac[s0];
        else          e = make_float2(NANF, (float)(s0 * 4096 + s1));
        g_lutf2[c] = e;
    }
    if (blockIdx.x == 0 && threadIdx.x == 0) {
        g_lutlo = lo;
        g_lutinv = (float)LUTN / (hi - lo);
    }
}

// ---- hot-path logit eval: 1 smem load (clean cell) or register end-coefs ----
__device__ __forceinline__ float eval_l(float x, const float2* __restrict__ slut,
                                        float lo, float inv,
                                        float2 ac0, float2 acN) {
    float fc = (x - lo) * inv;
    float2 ac;
    if (fc < 0.0f)                 ac = ac0;        // below all breakpoints
    else if (fc >= (float)LUTN)    ac = acN;        // above all breakpoints
    else {
        float2 e = slut[(int)fc];
        if (e.x == e.x) ac = e;                     // clean cell (not NaN)
        else {                                      // rare: binary search window
            int pk = (int)e.y;
            int a = pk >> 12, b = pk & 4095;
            while (a < b) { int m = (a + b) >> 1; if (__ldg(&g_bp[m]) <= x) a = m + 1; else b = m; }
            ac = g_ac[a];
        }
    }
    return fmaf(ac.x, x, ac.y);
}

// ---- online-softmax combine (order-fixed) ----
__device__ __forceinline__ void comb(float& m, float& S, float& q,
                                     float m2, float S2, float q2) {
    float mm = fmaxf(m, m2);
    float r1 = (m  == NEG_INF) ? 0.0f : __expf(m  - mm);
    float r2 = (m2 == NEG_INF) ? 0.0f : __expf(m2 - mm);
    S = S * r1 + S2 * r2;
    q = q * (r1 * r1) + q2 * (r2 * r2);
    m = mm;
}

// ===========================================================================
// passA: single read of g -> per-block (m, S, q, sum g^2)
// ===========================================================================
__global__ void __launch_bounds__(TPB) passA(const float* __restrict__ g, int N) {
    __shared__ float2 slut[LUTN];
    __shared__ float shm[8], shs[8], shq[8], shg[8];
    for (int i = threadIdx.x; i < LUTN; i += TPB) slut[i] = g_lutf2[i];
    float lo = g_lutlo, inv = g_lutinv;
    int nbp = g_nbp;
    float2 ac0 = g_ac[0], acN = g_ac[nbp];
    __syncthreads();

    float m = NEG_INF, S = 0.0f, q = 0.0f, g2 = 0.0f;
    int gt = blockIdx.x * blockDim.x + threadIdx.x;
    int stride = gridDim.x * blockDim.x;
    int N4 = N >> 2;
    const float4* g4 = (const float4*)g;
    for (int i = gt; i < N4; i += stride) {
        float4 v = g4[i];
        #pragma unroll
        for (int u = 0; u < 4; u++) {
            float x = (u == 0) ? v.x : (u == 1) ? v.y : (u == 2) ? v.z : v.w;
            g2 = fmaf(x, x, g2);
            float l = eval_l(x, slut, lo, inv, ac0, acN);
            if (l > m) { float r = __expf(m - l); S *= r; q *= r * r; m = l; }
            float e = __expf(l - m);
            S += e;
            float t = e * x;
            q = fmaf(t, t, q);
        }
    }
    for (int i = (N4 << 2) + gt; i < N; i += stride) {
        float x = g[i];
        g2 = fmaf(x, x, g2);
        float l = eval_l(x, slut, lo, inv, ac0, acN);
        if (l > m) { float r = __expf(m - l); S *= r; q *= r * r; m = l; }
        float e = __expf(l - m);
        S += e; float t = e * x; q = fmaf(t, t, q);
    }

    // warp reduce
    #pragma unroll
    for (int o = 16; o; o >>= 1) {
        float m2 = __shfl_down_sync(0xffffffffu, m, o);
        float S2 = __shfl_down_sync(0xffffffffu, S, o);
        float q2 = __shfl_down_sync(0xffffffffu, q, o);
        comb(m, S, q, m2, S2, q2);
        g2 += __shfl_down_sync(0xffffffffu, g2, o);
    }
    int w = threadIdx.x >> 5;
    if ((threadIdx.x & 31) == 0) { shm[w] = m; shs[w] = S; shq[w] = q; shg[w] = g2; }
    __syncthreads();
    if (threadIdx.x == 0) {
        float M = shm[0], SS = shs[0], Q = shq[0], G = shg[0];
        #pragma unroll
        for (int i = 1; i < TPB / 32; i++) { comb(M, SS, Q, shm[i], shs[i], shq[i]); G += shg[i]; }
        g_pm[blockIdx.x] = M; g_pS[blockIdx.x] = SS;
        g_pq[blockIdx.x] = Q; g_pg2[blockIdx.x] = G;
    }
}

// ===========================================================================
// kB: combine block partials -> g_m, g_kc
// ===========================================================================
__global__ void kB(const float* __restrict__ rescale) {
    __shared__ float sm[1024], sS[1024], sq[1024], sg[1024];
    int t = threadIdx.x;
    float m = NEG_INF, S = 0.0f, q = 0.0f, g2 = 0.0f;
    for (int i = t; i < GRID_MAIN; i += 1024) {
        comb(m, S, q, g_pm[i], g_pS[i], g_pq[i]);
        g2 += g_pg2[i];
    }
    sm[t] = m; sS[t] = S; sq[t] = q; sg[t] = g2;
    __syncthreads();
    for (int o = 512; o; o >>= 1) {
        if (t < o) {
            float M = sm[t], SS = sS[t], Q = sq[t];
            comb(M, SS, Q, sm[t + o], sS[t + o], sq[t + o]);
            sm[t] = M; sS[t] = SS; sq[t] = Q;
            sg[t] += sg[t + o];
        }
        __syncthreads();
    }
    if (t == 0) {
        float Sf = sS[0], qf = sq[0];
        float gn = sqrtf(sg[0]);
        float mnorm = sqrtf(qf) / Sf;
        float dyn = (mnorm > 1e-8f) ? gn / (mnorm + 1e-8f) : 1.0f;
        g_m  = sm[0];
        g_kc = rescale[0] * dyn / Sf;
    }
}

// ===========================================================================
// passC: out = kc * exp(l - m) * g
// ===========================================================================
__global__ void __launch_bounds__(TPB) passC(const float* __restrict__ g,
                                             float* __restrict__ out, int N) {
    __shared__ float2 slut[LUTN];
    for (int i = threadIdx.x; i < LUTN; i += TPB) slut[i] = g_lutf2[i];
    float lo = g_lutlo, inv = g_lutinv;
    int nbp = g_nbp;
    float2 ac0 = g_ac[0], acN = g_ac[nbp];
    float m = g_m, kc = g_kc;
    __syncthreads();

    int gt = blockIdx.x * blockDim.x + threadIdx.x;
    int stride = gridDim.x * blockDim.x;
    int N4 = N >> 2;
    const float4* g4 = (const float4*)g;
    float4* o4 = (float4*)out;
    for (int i = gt; i < N4; i += stride) {
        float4 v = g4[i];
        float4 r;
        r.x = kc * __expf(eval_l(v.x, slut, lo, inv, ac0, acN) - m) * v.x;
        r.y = kc * __expf(eval_l(v.y, slut, lo, inv, ac0, acN) - m) * v.y;
        r.z = kc * __expf(eval_l(v.z, slut, lo, inv, ac0, acN) - m) * v.z;
        r.w = kc * __expf(eval_l(v.w, slut, lo, inv, ac0, acN) - m) * v.w;
        o4[i] = r;
    }
    for (int i = (N4 << 2) + gt; i < N; i += stride) {
        float x = g[i];
        out[i] = kc * __expf(eval_l(x, slut, lo, inv, ac0, acN) - m) * x;
    }
}

// ===========================================================================
extern "C" void kernel_launch(void* const* d_in, const int* in_sizes, int n_in,
                              void* d_out, int out_size) {
    const float* grad    = (const float*)d_in[0];
    const float* W1      = (const float*)d_in[1];
    const float* b1      = (const float*)d_in[2];
    const float* W2      = (const float*)d_in[3];
    const float* b2      = (const float*)d_in[4];
    const float* W3      = (const float*)d_in[5];
    const float* b3      = (const float*)d_in[6];
    const float* rescale = (const float*)d_in[7];
    int N = in_sizes[0];

    k0a   <<<1, 32>>>(W1, b1);
    k0b   <<<9, 128>>>(W1, b1, W2, b2);
    k0sort<<<34, 1024>>>();
    k0d   <<<35, 1024>>>(W1, b1, W2, b2, W3, b3);
    k0lut <<<16, 128>>>();
    passA <<<GRID_MAIN, TPB>>>(grad, N);
    kB    <<<1, 1024>>>(rescale);
    passC <<<GRID_MAIN, TPB>>>(grad, (float*)d_out, N);
}